// round 9
// baseline (speedup 1.0000x reference)
#include <cuda_runtime.h>
#include <cuda_fp16.h>
#include <cstdint>
#include <math.h>

// Problem constants
#define B_   16
#define CIN  64
#define COUT 64
#define H_   128
#define W_   128
#define HW   (H_*W_)          // 16384
#define NPIX (B_*COUT*HW)     // 16,777,216

#define XPAD 72               // halves per px row (144 B): ldmatrix rows 16B-aligned
#define WPAD 72
#define XROW (132 * XPAD)     // halves per staged input row

// ---------------- device scratch (static, no allocation) ----------------
__device__ __align__(16) __half g_wh[25 * 64 * WPAD];   // [khw][cout][WPAD]
__device__ float g_dog[25];
__device__ __align__(16) float g_ybuf[NPIX];

__device__ __forceinline__ int refl(int i) {
    if (i < 0) return -i;
    if (i > 127) return 254 - i;
    return i;
}

__device__ __forceinline__ uint32_t smem_u32(const void* p) {
    uint32_t a;
    asm("{ .reg .u64 t; cvta.to.shared.u64 t, %1; cvt.u32.u64 %0, t; }"
        : "=r"(a) : "l"(p));
    return a;
}

// ---------------- kernel 1: weight prep (one block per cout) ----------------
__global__ __launch_bounds__(128)
void prep_kernel(const float* __restrict__ w) {
    __shared__ float ws[1600];
    __shared__ float invn[25];
    const int tid = threadIdx.x;
    const int o = blockIdx.x;

    for (int i = tid; i < 1600; i += 128) ws[i] = w[o * 1600 + i];
    __syncthreads();
    if (tid < 25) {
        float s = 0.f;
        #pragma unroll 8
        for (int ci = 0; ci < CIN; ci++) {
            float v = ws[ci * 25 + tid];
            s += v * v;
        }
        invn[tid] = 1.f / fmaxf(sqrtf(s), 1e-12f);
    }
    __syncthreads();
    for (int i = tid; i < 1600; i += 128) {
        int khw = i >> 6, ci = i & 63;
        float v = fabsf(ws[ci * 25 + khw]) * invn[khw];
        g_wh[(size_t)(khw * 64 + o) * WPAD + ci] = __float2half(v);
    }
    if (o == 0 && tid < 25) {
        int u = tid / 5 - 2, v = tid % 5 - 2;
        float d2 = (float)(u * u + v * v);
        const float two_pi = 6.2831853071795864769f;
        const float ae = 1.f / (two_pi * 1.44f);   // sigma_e = 1.2
        const float ai = 1.f / (two_pi * 1.96f);   // sigma_i = 1.4
        float val = ae * expf(-d2 / (2.f * 1.44f)) - ai * expf(-d2 / (2.f * 1.96f));
        g_dog[tid] = val / (ae - ai);
    }
}

// ---------------- kernel 2: fp16 HMMA implicit-GEMM conv + cosine ----------------
// Grid (64, 16): CTA = 2 output y-rows x 128 px x 64 cout. 512 thr = 16 warps.
// Warp = (n-half nh = w>>3, px block blk = w&7): yrow g = blk>>2, px0 = (blk&3)*32,
// n0 = nh*32. Warp tile M32 (1 row x 32 px) x N32. 4 warps/SMSP.
// smem: Ws[5kw][64][WPAD] 46080 | Xs[6 rows][132 px][XPAD] 114048 | Crow[6*132] | Ssum[2*132]
#define WS_BYTES (5 * 64 * WPAD * 2)            // 46080
#define XS_BYTES (6 * 132 * XPAD * 2)           // 114048
#define CROW_FLOATS (6 * 132)
#define SSUM_FLOATS (2 * 132)
#define DSMEM (WS_BYTES + XS_BYTES + (CROW_FLOATS + SSUM_FLOATS) * 4)  // 168480

__global__ __launch_bounds__(512, 1)
void main_mma_kernel(const float* __restrict__ x) {
    extern __shared__ char dsm[];
    __half* Ws   = (__half*)dsm;
    __half* Xs   = (__half*)(dsm + WS_BYTES);
    float*  Crow = (float*)(dsm + WS_BYTES + XS_BYTES);
    float*  Ssum = Crow + CROW_FLOATS;

    const int tid  = threadIdx.x;
    const int warp = tid >> 5;
    const int lane = tid & 31;
    const int nh   = warp >> 3;           // n half 0..1
    const int blk  = warp & 7;            // px block 0..7
    const int g    = blk >> 2;            // output yrow 0..1
    const int px0  = (blk & 3) * 32;      // px offset within row
    const int n0   = nh * 32;             // cout offset
    const int b    = blockIdx.y;
    const int y0   = blockIdx.x * 2;

    // ---- stage X once: 6 input rows, transpose [ci][px] -> [px][ci] ----
    for (int task = warp; task < 96; task += 16) {
        int s = task >> 4, q = task & 15;
        int gy = refl(y0 + s - 2);
        const float* base = x + ((size_t)b * CIN + q * 4) * HW + (size_t)gy * W_;
        #pragma unroll
        for (int k = 0; k < 5; k++) {
            int c = lane + 32 * k;
            if (c < 132) {
                int gc = refl(c - 2);
                float v0 = base[0 * HW + gc];
                float v1 = base[1 * HW + gc];
                float v2 = base[2 * HW + gc];
                float v3 = base[3 * HW + gc];
                uint32_t p0, p1;
                asm("cvt.rn.f16x2.f32 %0, %1, %2;" : "=r"(p0) : "f"(v1), "f"(v0));
                asm("cvt.rn.f16x2.f32 %0, %1, %2;" : "=r"(p1) : "f"(v3), "f"(v2));
                *(uint2*)(Xs + (size_t)s * XROW + (size_t)c * XPAD + q * 4) =
                    make_uint2(p0, p1);
            }
        }
    }
    __syncthreads();

    // ---- per staged-row column sums of x^2 ----
    for (int t = tid; t < 792; t += 512) {
        int s = t / 132, c = t - s * 132;
        const uint4* p = (const uint4*)(Xs + (size_t)s * XROW + (size_t)c * XPAD);
        float sacc = 0.f;
        #pragma unroll
        for (int i = 0; i < 8; i++) {
            uint4 u = p[i];
            const uint32_t uu[4] = {u.x, u.y, u.z, u.w};
            #pragma unroll
            for (int j = 0; j < 4; j++) {
                float2 f = __half22float2(*(const __half2*)&uu[j]);
                sacc = fmaf(f.x, f.x, fmaf(f.y, f.y, sacc));
            }
        }
        Crow[t] = sacc;
    }
    __syncthreads();

    // ---- 5-row window sums -> Ssum[out row][padded col] ----
    for (int t = tid; t < 264; t += 512) {
        int r = t / 132, c = t - r * 132;
        Ssum[t] = Crow[(r + 0) * 132 + c] + Crow[(r + 1) * 132 + c]
                + Crow[(r + 2) * 132 + c] + Crow[(r + 3) * 132 + c]
                + Crow[(r + 4) * 132 + c];
    }

    // ---- accumulators: [mt = px half][nt = 8-col group within N32][4] ----
    float acc[2][4][4];
    #pragma unroll
    for (int mt = 0; mt < 2; mt++)
        #pragma unroll
        for (int nt = 0; nt < 4; nt++)
            #pragma unroll
            for (int i = 0; i < 4; i++) acc[mt][nt][i] = 0.f;

    // ldmatrix lane mappings (verified R5/R6)
    const int m_off = ((lane >> 3) & 1) * 8 + (lane & 7);      // A rows
    const int k_off = (lane >> 4) * 8;                          // A k segment
    const int brow  = (lane & 7) + ((lane >> 4) << 3);          // B n row
    const int bk    = ((lane >> 3) & 1) * 8;                    // B k segment

    for (int kh = 0; kh < 5; kh++) {
        __syncthreads();   // previous kh's taps done reading Ws
        {
            const uint4* src = (const uint4*)(g_wh + (size_t)kh * 5 * 64 * WPAD);
            uint4* dst = (uint4*)Ws;
            for (int i = tid; i < 2880; i += 512) dst[i] = src[i];
        }
        __syncthreads();

        #pragma unroll
        for (int kw = 0; kw < 5; kw++) {
            const __half* Ab = Xs + (size_t)(g + kh) * XROW
                                  + (size_t)(px0 + kw) * XPAD;
            #pragma unroll
            for (int kt = 0; kt < 4; kt++) {
                uint32_t a[2][4];
                #pragma unroll
                for (int mt = 0; mt < 2; mt++) {
                    uint32_t ad = smem_u32(Ab + (size_t)(mt * 16 + m_off) * XPAD
                                              + kt * 16 + k_off);
                    asm volatile(
                        "ldmatrix.sync.aligned.m8n8.x4.shared.b16 {%0,%1,%2,%3}, [%4];"
                        : "=r"(a[mt][0]), "=r"(a[mt][1]), "=r"(a[mt][2]), "=r"(a[mt][3])
                        : "r"(ad));
                }
                #pragma unroll
                for (int np = 0; np < 2; np++) {
                    uint32_t bb[4];
                    uint32_t bd = smem_u32(Ws + (size_t)(kw * 64 + n0 + np * 16 + brow) * WPAD
                                              + kt * 16 + bk);
                    asm volatile(
                        "ldmatrix.sync.aligned.m8n8.x4.shared.b16 {%0,%1,%2,%3}, [%4];"
                        : "=r"(bb[0]), "=r"(bb[1]), "=r"(bb[2]), "=r"(bb[3])
                        : "r"(bd));
                    #pragma unroll
                    for (int mt = 0; mt < 2; mt++) {
                        asm volatile(
                            "mma.sync.aligned.m16n8k16.row.col.f32.f16.f16.f32 "
                            "{%0,%1,%2,%3}, {%4,%5,%6,%7}, {%8,%9}, {%0,%1,%2,%3};"
                            : "+f"(acc[mt][2 * np][0]), "+f"(acc[mt][2 * np][1]),
                              "+f"(acc[mt][2 * np][2]), "+f"(acc[mt][2 * np][3])
                            : "r"(a[mt][0]), "r"(a[mt][1]), "r"(a[mt][2]), "r"(a[mt][3]),
                              "r"(bb[0]), "r"(bb[1]));
                        asm volatile(
                            "mma.sync.aligned.m16n8k16.row.col.f32.f16.f16.f32 "
                            "{%0,%1,%2,%3}, {%4,%5,%6,%7}, {%8,%9}, {%0,%1,%2,%3};"
                            : "+f"(acc[mt][2 * np + 1][0]), "+f"(acc[mt][2 * np + 1][1]),
                              "+f"(acc[mt][2 * np + 1][2]), "+f"(acc[mt][2 * np + 1][3])
                            : "r"(a[mt][0]), "r"(a[mt][1]), "r"(a[mt][2]), "r"(a[mt][3]),
                              "r"(bb[2]), "r"(bb[3]));
                    }
                }
            }
        }
    }
    __syncthreads();   // all taps done; smem (except Ssum at tail) reusable

    // ---- epilogue: cosine norm + per-warp smem transpose + coalesced store ----
    float inv[2][2];   // [mt][h]
    #pragma unroll
    for (int mt = 0; mt < 2; mt++)
        #pragma unroll
        for (int h = 0; h < 2; h++) {
            int p = px0 + mt * 16 + (lane >> 2) + h * 8;   // output px
            const float* sp = Ssum + g * 132 + p;           // window p..p+4
            float s = sp[0] + sp[1] + sp[2] + sp[3] + sp[4];
            inv[mt][h] = rsqrtf(s + 1e-8f);
        }

    // per-warp buf [32 cout][36 px-pad] (16 warps * 4608 B = 73728 B at dsm base)
    float* buf = (float*)dsm + warp * (32 * 36);
    #pragma unroll
    for (int mt = 0; mt < 2; mt++)
        #pragma unroll
        for (int nt = 0; nt < 4; nt++)
            #pragma unroll
            for (int reg = 0; reg < 4; reg++) {
                int co  = nt * 8 + (lane & 3) * 2 + (reg & 1);      // 0..31
                int pxl = mt * 16 + (lane >> 2) + (reg >> 1) * 8;   // 0..31
                buf[co * 36 + pxl] = acc[mt][nt][reg] * inv[mt][reg >> 1];
            }
    __syncwarp();

    const int y = y0 + g;
    #pragma unroll
    for (int it = 0; it < 8; it++) {
        int row = it * 4 + (lane >> 3);   // cout local 0..31
        int seg = lane & 7;               // 4-px segment
        float4 v = *(const float4*)&buf[row * 36 + seg * 4];
        *(float4*)&g_ybuf[(((size_t)b * COUT + n0 + row) * H_ + y) * W_ + px0 + seg * 4] = v;
    }
}

// ---------------- kernel 3: depthwise 5x5 DoG (zero pad) ----------------
__global__ __launch_bounds__(512)
void dog_kernel(float* __restrict__ out) {
    __shared__ float Ts[20 * 132];
    __shared__ float sd[25];

    const int tid = threadIdx.x;
    const int bc  = blockIdx.x;
    const int y0  = blockIdx.y * 16;

    if (tid < 25) sd[tid] = g_dog[tid];

    const float* src = g_ybuf + (size_t)bc * HW;
    for (int idx = tid; idx < 20 * 132; idx += 512) {
        int rr = idx / 132;
        int c  = idx - rr * 132;
        int gy = y0 + rr - 2;
        int gx = c - 2;
        float v = 0.f;
        if (gy >= 0 && gy < H_ && gx >= 0 && gx < W_) v = src[gy * W_ + gx];
        Ts[idx] = v;
    }
    __syncthreads();

    const int row = tid >> 5;
    const int t4  = (tid & 31) * 4;
    float a[4] = {0.f, 0.f, 0.f, 0.f};

    #pragma unroll
    for (int u = 0; u < 5; u++) {
        const float* rp = &Ts[(row + u) * 132 + t4];
        float4 xa = *(const float4*)rp;
        float4 xc = *(const float4*)(rp + 4);
        float xv[8] = {xa.x, xa.y, xa.z, xa.w, xc.x, xc.y, xc.z, xc.w};
        #pragma unroll
        for (int v = 0; v < 5; v++) {
            float dv = sd[u * 5 + v];
            #pragma unroll
            for (int j = 0; j < 4; j++) a[j] = fmaf(dv, xv[v + j], a[j]);
        }
    }
    float4 o = make_float4(a[0], a[1], a[2], a[3]);
    *(float4*)&out[(size_t)bc * HW + (y0 + row) * W_ + t4] = o;
}

// ---------------- launch ----------------
extern "C" void kernel_launch(void* const* d_in, const int* in_sizes, int n_in,
                              void* d_out, int out_size) {
    const float* x = (const float*)d_in[0];
    const float* w = (const float*)d_in[1];
    float* out = (float*)d_out;

    static bool attr_set = false;
    if (!attr_set) {
        cudaFuncSetAttribute(main_mma_kernel,
                             cudaFuncAttributeMaxDynamicSharedMemorySize, DSMEM);
        attr_set = true;
    }

    prep_kernel<<<64, 128>>>(w);
    main_mma_kernel<<<dim3(64, 16), 512, DSMEM>>>(x);
    dog_kernel<<<dim3(1024, 8), 512>>>(out);
}

// round 12
// speedup vs baseline: 1.8418x; 1.8418x over previous
#include <cuda_runtime.h>
#include <cuda_fp16.h>
#include <cstdint>
#include <math.h>

// Problem constants
#define B_   16
#define CIN  64
#define COUT 64
#define H_   128
#define W_   128
#define HW   (H_*W_)          // 16384
#define NPIX (B_*COUT*HW)     // 16,777,216

#define XPAD 72               // halves per px row (144 B): ldmatrix rows 16B-aligned
#define WPAD 72
#define XROW (132 * XPAD)     // halves per staged input row

// ---------------- device scratch (static, no allocation) ----------------
__device__ __align__(16) __half g_wh[25 * 64 * WPAD];   // [khw][cout][WPAD]
__device__ float g_dog[25];
__device__ __align__(16) __half g_ybuf[NPIX];           // fp16 cosine-sim intermediate

__device__ __forceinline__ int refl(int i) {
    if (i < 0) return -i;
    if (i > 127) return 254 - i;
    return i;
}

__device__ __forceinline__ uint32_t smem_u32(const void* p) {
    uint32_t a;
    asm("{ .reg .u64 t; cvta.to.shared.u64 t, %1; cvt.u32.u64 %0, t; }"
        : "=r"(a) : "l"(p));
    return a;
}

// ---------------- kernel 1: weight prep (one block per cout) ----------------
__global__ __launch_bounds__(128)
void prep_kernel(const float* __restrict__ w) {
    __shared__ float ws[1600];
    __shared__ float psum[25][4];
    __shared__ float invn[25];
    const int tid = threadIdx.x;
    const int o = blockIdx.x;

    for (int i = tid; i < 1600; i += 128) ws[i] = w[o * 1600 + i];
    __syncthreads();
    // partial norms: 100 threads, each sums 16 ci for one (khw, quarter)
    if (tid < 100) {
        int khw = tid >> 2, q = tid & 3;
        float s = 0.f;
        #pragma unroll
        for (int j = 0; j < 16; j++) {
            float v = ws[(q * 16 + j) * 25 + khw];
            s += v * v;
        }
        psum[khw][q] = s;
    }
    __syncthreads();
    if (tid < 25) {
        float s = psum[tid][0] + psum[tid][1] + psum[tid][2] + psum[tid][3];
        invn[tid] = 1.f / fmaxf(sqrtf(s), 1e-12f);
    }
    __syncthreads();
    for (int i = tid; i < 1600; i += 128) {
        int khw = i >> 6, ci = i & 63;
        float v = fabsf(ws[ci * 25 + khw]) * invn[khw];
        g_wh[(size_t)(khw * 64 + o) * WPAD + ci] = __float2half(v);
    }
    if (o == 0 && tid < 25) {
        int u = tid / 5 - 2, v = tid % 5 - 2;
        float d2 = (float)(u * u + v * v);
        const float two_pi = 6.2831853071795864769f;
        const float ae = 1.f / (two_pi * 1.44f);   // sigma_e = 1.2
        const float ai = 1.f / (two_pi * 1.96f);   // sigma_i = 1.4
        float val = ae * expf(-d2 / (2.f * 1.44f)) - ai * expf(-d2 / (2.f * 1.96f));
        g_dog[tid] = val / (ae - ai);
    }
}

// ---------------- kernel 2: fp16 HMMA implicit-GEMM conv + cosine (R6 config) ----------------
// Grid (32, 16): CTA = 4 output y-rows x 128 px x 64 cout. 512 thr = 16 warps.
// Warp w: yrow g = w>>2, px block (w&3)*32. Warp tile M32 x N64. X staged ONCE (8 rows).
// smem: Ws[5kw][64][WPAD] 46080 | Xs[8 rows][132 px][XPAD] 152064 | Crow[8*132] | Ssum[4*132]
#define WS_BYTES (5 * 64 * WPAD * 2)            // 46080
#define XS_BYTES (8 * 132 * XPAD * 2)           // 152064
#define CROW_FLOATS (8 * 132)
#define SSUM_FLOATS (4 * 132)
#define DSMEM (WS_BYTES + XS_BYTES + (CROW_FLOATS + SSUM_FLOATS) * 4)  // 204480

__global__ __launch_bounds__(512, 1)
void main_mma_kernel(const float* __restrict__ x) {
    extern __shared__ char dsm[];
    __half* Ws   = (__half*)dsm;
    __half* Xs   = (__half*)(dsm + WS_BYTES);
    float*  Crow = (float*)(dsm + WS_BYTES + XS_BYTES);
    float*  Ssum = Crow + CROW_FLOATS;

    const int tid  = threadIdx.x;
    const int warp = tid >> 5;
    const int lane = tid & 31;
    const int g    = warp >> 2;           // output yrow 0..3
    const int px0  = (warp & 3) * 32;     // pixel block
    const int b    = blockIdx.y;
    const int y0   = blockIdx.x * 4;

    // ---- stage X once: 8 input rows, transpose [ci][px] -> [px][ci] ----
    for (int task = warp; task < 128; task += 16) {
        int s = task >> 4, q = task & 15;
        int gy = refl(y0 + s - 2);
        const float* base = x + ((size_t)b * CIN + q * 4) * HW + (size_t)gy * W_;
        #pragma unroll
        for (int k = 0; k < 5; k++) {
            int c = lane + 32 * k;
            if (c < 132) {
                int gc = refl(c - 2);
                float v0 = base[0 * HW + gc];
                float v1 = base[1 * HW + gc];
                float v2 = base[2 * HW + gc];
                float v3 = base[3 * HW + gc];
                uint32_t p0, p1;
                asm("cvt.rn.f16x2.f32 %0, %1, %2;" : "=r"(p0) : "f"(v1), "f"(v0));
                asm("cvt.rn.f16x2.f32 %0, %1, %2;" : "=r"(p1) : "f"(v3), "f"(v2));
                *(uint2*)(Xs + (size_t)s * XROW + (size_t)c * XPAD + q * 4) =
                    make_uint2(p0, p1);
            }
        }
    }
    __syncthreads();

    // ---- per staged-row column sums of x^2 ----
    for (int t = tid; t < 1056; t += 512) {
        int s = t / 132, c = t - s * 132;
        const uint4* p = (const uint4*)(Xs + (size_t)s * XROW + (size_t)c * XPAD);
        float sacc = 0.f;
        #pragma unroll
        for (int i = 0; i < 8; i++) {
            uint4 u = p[i];
            const uint32_t uu[4] = {u.x, u.y, u.z, u.w};
            #pragma unroll
            for (int j = 0; j < 4; j++) {
                float2 f = __half22float2(*(const __half2*)&uu[j]);
                sacc = fmaf(f.x, f.x, fmaf(f.y, f.y, sacc));
            }
        }
        Crow[t] = sacc;
    }
    __syncthreads();

    // ---- 5-row window sums -> Ssum[out row][padded col] ----
    for (int t = tid; t < 528; t += 512) {
        int r = t / 132, c = t - r * 132;
        Ssum[t] = Crow[(r + 0) * 132 + c] + Crow[(r + 1) * 132 + c]
                + Crow[(r + 2) * 132 + c] + Crow[(r + 3) * 132 + c]
                + Crow[(r + 4) * 132 + c];
    }

    // ---- accumulators ----
    float acc[2][8][4];
    #pragma unroll
    for (int mt = 0; mt < 2; mt++)
        #pragma unroll
        for (int nt = 0; nt < 8; nt++)
            #pragma unroll
            for (int i = 0; i < 4; i++) acc[mt][nt][i] = 0.f;

    // ldmatrix lane mappings (verified R5/R6)
    const int m_off = ((lane >> 3) & 1) * 8 + (lane & 7);      // A rows
    const int k_off = (lane >> 4) * 8;                          // A k segment
    const int brow  = (lane & 7) + ((lane >> 4) << 3);          // B n row
    const int bk    = ((lane >> 3) & 1) * 8;                    // B k segment

    for (int kh = 0; kh < 5; kh++) {
        __syncthreads();   // previous kh's taps done reading Ws
        {
            const uint4* src = (const uint4*)(g_wh + (size_t)kh * 5 * 64 * WPAD);
            uint4* dst = (uint4*)Ws;
            for (int i = tid; i < 2880; i += 512) dst[i] = src[i];
        }
        __syncthreads();

        #pragma unroll
        for (int kw = 0; kw < 5; kw++) {
            const __half* Ab = Xs + (size_t)(g + kh) * XROW
                                  + (size_t)(px0 + kw) * XPAD;
            // A fragments for all 4 k-chunks
            uint32_t a[4][2][4];
            #pragma unroll
            for (int kt = 0; kt < 4; kt++)
                #pragma unroll
                for (int mt = 0; mt < 2; mt++) {
                    uint32_t ad = smem_u32(Ab + (size_t)(mt * 16 + m_off) * XPAD
                                              + kt * 16 + k_off);
                    asm volatile(
                        "ldmatrix.sync.aligned.m8n8.x4.shared.b16 {%0,%1,%2,%3}, [%4];"
                        : "=r"(a[kt][mt][0]), "=r"(a[kt][mt][1]),
                          "=r"(a[kt][mt][2]), "=r"(a[kt][mt][3])
                        : "r"(ad));
                }
            // B via ldmatrix.x4: regs = {b0,b1 of nt even; b0,b1 of nt odd}
            #pragma unroll
            for (int np = 0; np < 4; np++) {
                #pragma unroll
                for (int kt = 0; kt < 4; kt++) {
                    uint32_t bb[4];
                    uint32_t bd = smem_u32(Ws + (size_t)(kw * 64 + np * 16 + brow) * WPAD
                                              + kt * 16 + bk);
                    asm volatile(
                        "ldmatrix.sync.aligned.m8n8.x4.shared.b16 {%0,%1,%2,%3}, [%4];"
                        : "=r"(bb[0]), "=r"(bb[1]), "=r"(bb[2]), "=r"(bb[3])
                        : "r"(bd));
                    #pragma unroll
                    for (int mt = 0; mt < 2; mt++) {
                        asm volatile(
                            "mma.sync.aligned.m16n8k16.row.col.f32.f16.f16.f32 "
                            "{%0,%1,%2,%3}, {%4,%5,%6,%7}, {%8,%9}, {%0,%1,%2,%3};"
                            : "+f"(acc[mt][2 * np][0]), "+f"(acc[mt][2 * np][1]),
                              "+f"(acc[mt][2 * np][2]), "+f"(acc[mt][2 * np][3])
                            : "r"(a[kt][mt][0]), "r"(a[kt][mt][1]),
                              "r"(a[kt][mt][2]), "r"(a[kt][mt][3]),
                              "r"(bb[0]), "r"(bb[1]));
                        asm volatile(
                            "mma.sync.aligned.m16n8k16.row.col.f32.f16.f16.f32 "
                            "{%0,%1,%2,%3}, {%4,%5,%6,%7}, {%8,%9}, {%0,%1,%2,%3};"
                            : "+f"(acc[mt][2 * np + 1][0]), "+f"(acc[mt][2 * np + 1][1]),
                              "+f"(acc[mt][2 * np + 1][2]), "+f"(acc[mt][2 * np + 1][3])
                            : "r"(a[kt][mt][0]), "r"(a[kt][mt][1]),
                              "r"(a[kt][mt][2]), "r"(a[kt][mt][3]),
                              "r"(bb[2]), "r"(bb[3]));
                    }
                }
            }
        }
    }
    __syncthreads();   // all taps done; Xs region reusable for epilogue

    // ---- epilogue: cosine norm + smem transpose + coalesced fp16 store ----
    float inv[2][2];
    #pragma unroll
    for (int mt = 0; mt < 2; mt++)
        #pragma unroll
        for (int h = 0; h < 2; h++) {
            int p = px0 + mt * 16 + (lane >> 2) + h * 8;
            const float* sp = Ssum + g * 132 + p;
            float s = sp[0] + sp[1] + sp[2] + sp[3] + sp[4];
            inv[mt][h] = rsqrtf(s + 1e-8f);
        }

    float* buf = (float*)(dsm + WS_BYTES) + warp * (64 * 36);
    #pragma unroll
    for (int mt = 0; mt < 2; mt++)
        #pragma unroll
        for (int nt = 0; nt < 8; nt++)
            #pragma unroll
            for (int reg = 0; reg < 4; reg++) {
                int co  = nt * 8 + (lane & 3) * 2 + (reg & 1);
                int pxl = mt * 16 + (lane >> 2) + (reg >> 1) * 8;
                buf[co * 36 + pxl] = acc[mt][nt][reg] * inv[mt][reg >> 1];
            }
    __syncwarp();

    const int y = y0 + g;
    #pragma unroll
    for (int it = 0; it < 16; it++) {
        int row = it * 4 + (lane >> 3);   // cout
        int seg = lane & 7;               // 4-px segment
        float4 v = *(const float4*)&buf[row * 36 + seg * 4];
        uint32_t h01, h23;
        asm("cvt.rn.f16x2.f32 %0, %1, %2;" : "=r"(h01) : "f"(v.y), "f"(v.x));
        asm("cvt.rn.f16x2.f32 %0, %1, %2;" : "=r"(h23) : "f"(v.w), "f"(v.z));
        *(uint2*)&g_ybuf[(((size_t)b * COUT + row) * H_ + y) * W_ + px0 + seg * 4] =
            make_uint2(h01, h23);
    }
}

// ---------------- kernel 3: depthwise 5x5 DoG (zero pad), fp16 input ----------------
__global__ __launch_bounds__(512)
void dog_kernel(float* __restrict__ out) {
    __shared__ float Ts[20 * 132];
    __shared__ float sd[25];

    const int tid = threadIdx.x;
    const int bc  = blockIdx.x;
    const int y0  = blockIdx.y * 16;

    if (tid < 25) sd[tid] = g_dog[tid];

    const __half* src = g_ybuf + (size_t)bc * HW;
    // interior rows: vectorized half2 loads (2 px per thread-step)
    for (int idx = tid; idx < 20 * 66; idx += 512) {
        int rr = idx / 66;
        int c2 = (idx - rr * 66) * 2;         // padded col pair base (0,2,...,130)
        int gy = y0 + rr - 2;
        float2 f = make_float2(0.f, 0.f);
        if (gy >= 0 && gy < H_) {
            int gx = c2 - 2;
            if (gx >= 0 && gx + 1 < W_) {
                f = __half22float2(*(const __half2*)(src + gy * W_ + gx));
            } else {
                if (gx >= 0 && gx < W_)         f.x = __half2float(src[gy * W_ + gx]);
                if (gx + 1 >= 0 && gx + 1 < W_) f.y = __half2float(src[gy * W_ + gx + 1]);
            }
        }
        Ts[rr * 132 + c2]     = f.x;
        Ts[rr * 132 + c2 + 1] = f.y;
    }
    __syncthreads();

    const int row = tid >> 5;
    const int t4  = (tid & 31) * 4;
    float a[4] = {0.f, 0.f, 0.f, 0.f};

    #pragma unroll
    for (int u = 0; u < 5; u++) {
        const float* rp = &Ts[(row + u) * 132 + t4];
        float4 xa = *(const float4*)rp;
        float4 xc = *(const float4*)(rp + 4);
        float xv[8] = {xa.x, xa.y, xa.z, xa.w, xc.x, xc.y, xc.z, xc.w};
        #pragma unroll
        for (int v = 0; v < 5; v++) {
            float dv = sd[u * 5 + v];
            #pragma unroll
            for (int j = 0; j < 4; j++) a[j] = fmaf(dv, xv[v + j], a[j]);
        }
    }
    float4 o = make_float4(a[0], a[1], a[2], a[3]);
    *(float4*)&out[(size_t)bc * HW + (y0 + row) * W_ + t4] = o;
}

// ---------------- launch ----------------
extern "C" void kernel_launch(void* const* d_in, const int* in_sizes, int n_in,
                              void* d_out, int out_size) {
    const float* x = (const float*)d_in[0];
    const float* w = (const float*)d_in[1];
    float* out = (float*)d_out;

    static bool attr_set = false;
    if (!attr_set) {
        cudaFuncSetAttribute(main_mma_kernel,
                             cudaFuncAttributeMaxDynamicSharedMemorySize, DSMEM);
        attr_set = true;
    }

    prep_kernel<<<64, 128>>>(w);
    main_mma_kernel<<<dim3(32, 16), 512, DSMEM>>>(x);
    dog_kernel<<<dim3(1024, 8), 512>>>(out);
}

// round 13
// speedup vs baseline: 1.8559x; 1.0076x over previous
#include <cuda_runtime.h>
#include <cuda_fp16.h>
#include <cstdint>
#include <math.h>

// Problem constants
#define B_   16
#define CIN  64
#define COUT 64
#define H_   128
#define W_   128
#define HW   (H_*W_)          // 16384
#define NPIX (B_*COUT*HW)     // 16,777,216

#define XPAD 72               // halves per px row (144 B): ldmatrix rows 16B-aligned
#define WPAD 72
#define XROW (132 * XPAD)     // halves per staged input row

// ---------------- device scratch (static, no allocation) ----------------
__device__ __align__(16) __half g_wh[25 * 64 * WPAD];   // [khw][cout][WPAD]
__device__ float g_dog[25];
__device__ __align__(16) __half g_ybuf[NPIX];           // fp16 cosine-sim intermediate

__device__ __forceinline__ int refl(int i) {
    if (i < 0) return -i;
    if (i > 127) return 254 - i;
    return i;
}

__device__ __forceinline__ uint32_t smem_u32(const void* p) {
    uint32_t a;
    asm("{ .reg .u64 t; cvta.to.shared.u64 t, %1; cvt.u32.u64 %0, t; }"
        : "=r"(a) : "l"(p));
    return a;
}

// ---------------- kernel 1: weight prep (one block per (cout, tap)) ----------------
// grid 1600, block 64: thread = ci. One LDG -> shfl reduce -> coalesced half store.
__global__ __launch_bounds__(64)
void prep_kernel(const float* __restrict__ w) {
    __shared__ float sh[2];
    const int tid = threadIdx.x;          // ci
    const int o   = blockIdx.x / 25;
    const int khw = blockIdx.x % 25;

    float v = w[o * 1600 + tid * 25 + khw];
    float s = v * v;
    #pragma unroll
    for (int off = 16; off > 0; off >>= 1)
        s += __shfl_down_sync(0xFFFFFFFFu, s, off);
    if ((tid & 31) == 0) sh[tid >> 5] = s;
    __syncthreads();
    float tot = sh[0] + sh[1];
    float inv = 1.f / fmaxf(sqrtf(tot), 1e-12f);
    g_wh[(size_t)(khw * 64 + o) * WPAD + tid] = __float2half(fabsf(v) * inv);

    if (blockIdx.x == 0 && tid < 25) {
        int u = tid / 5 - 2, vv = tid % 5 - 2;
        float d2 = (float)(u * u + vv * vv);
        const float two_pi = 6.2831853071795864769f;
        const float ae = 1.f / (two_pi * 1.44f);   // sigma_e = 1.2
        const float ai = 1.f / (two_pi * 1.96f);   // sigma_i = 1.4
        float val = ae * expf(-d2 / (2.f * 1.44f)) - ai * expf(-d2 / (2.f * 1.96f));
        g_dog[tid] = val / (ae - ai);
    }
}

// ---------------- kernel 2: fp16 HMMA implicit-GEMM conv + cosine (R6 config) ----------------
// Grid (32, 16): CTA = 4 output y-rows x 128 px x 64 cout. 512 thr = 16 warps.
// Warp w: yrow g = w>>2, px block (w&3)*32. Warp tile M32 x N64. X staged ONCE (8 rows).
// smem: Ws[5kw][64][WPAD] 46080 | Xs[8 rows][132 px][XPAD] 152064 | Crow[8*132] | Ssum[4*132]
#define WS_BYTES (5 * 64 * WPAD * 2)            // 46080
#define XS_BYTES (8 * 132 * XPAD * 2)           // 152064
#define CROW_FLOATS (8 * 132)
#define SSUM_FLOATS (4 * 132)
#define DSMEM (WS_BYTES + XS_BYTES + (CROW_FLOATS + SSUM_FLOATS) * 4)  // 204480

__global__ __launch_bounds__(512, 1)
void main_mma_kernel(const float* __restrict__ x) {
    extern __shared__ char dsm[];
    __half* Ws   = (__half*)dsm;
    __half* Xs   = (__half*)(dsm + WS_BYTES);
    float*  Crow = (float*)(dsm + WS_BYTES + XS_BYTES);
    float*  Ssum = Crow + CROW_FLOATS;

    const int tid  = threadIdx.x;
    const int warp = tid >> 5;
    const int lane = tid & 31;
    const int g    = warp >> 2;           // output yrow 0..3
    const int px0  = (warp & 3) * 32;     // pixel block
    const int b    = blockIdx.y;
    const int y0   = blockIdx.x * 4;

    // ---- stage X once: 8 input rows, transpose [ci][px] -> [px][ci] ----
    for (int task = warp; task < 128; task += 16) {
        int s = task >> 4, q = task & 15;
        int gy = refl(y0 + s - 2);
        const float* base = x + ((size_t)b * CIN + q * 4) * HW + (size_t)gy * W_;
        #pragma unroll
        for (int k = 0; k < 5; k++) {
            int c = lane + 32 * k;
            if (c < 132) {
                int gc = refl(c - 2);
                float v0 = base[0 * HW + gc];
                float v1 = base[1 * HW + gc];
                float v2 = base[2 * HW + gc];
                float v3 = base[3 * HW + gc];
                uint32_t p0, p1;
                asm("cvt.rn.f16x2.f32 %0, %1, %2;" : "=r"(p0) : "f"(v1), "f"(v0));
                asm("cvt.rn.f16x2.f32 %0, %1, %2;" : "=r"(p1) : "f"(v3), "f"(v2));
                *(uint2*)(Xs + (size_t)s * XROW + (size_t)c * XPAD + q * 4) =
                    make_uint2(p0, p1);
            }
        }
    }
    __syncthreads();

    // ---- per staged-row column sums of x^2 ----
    for (int t = tid; t < 1056; t += 512) {
        int s = t / 132, c = t - s * 132;
        const uint4* p = (const uint4*)(Xs + (size_t)s * XROW + (size_t)c * XPAD);
        float sacc = 0.f;
        #pragma unroll
        for (int i = 0; i < 8; i++) {
            uint4 u = p[i];
            const uint32_t uu[4] = {u.x, u.y, u.z, u.w};
            #pragma unroll
            for (int j = 0; j < 4; j++) {
                float2 f = __half22float2(*(const __half2*)&uu[j]);
                sacc = fmaf(f.x, f.x, fmaf(f.y, f.y, sacc));
            }
        }
        Crow[t] = sacc;
    }
    __syncthreads();

    // ---- 5-row window sums -> Ssum[out row][padded col] ----
    for (int t = tid; t < 528; t += 512) {
        int r = t / 132, c = t - r * 132;
        Ssum[t] = Crow[(r + 0) * 132 + c] + Crow[(r + 1) * 132 + c]
                + Crow[(r + 2) * 132 + c] + Crow[(r + 3) * 132 + c]
                + Crow[(r + 4) * 132 + c];
    }

    // ---- accumulators ----
    float acc[2][8][4];
    #pragma unroll
    for (int mt = 0; mt < 2; mt++)
        #pragma unroll
        for (int nt = 0; nt < 8; nt++)
            #pragma unroll
            for (int i = 0; i < 4; i++) acc[mt][nt][i] = 0.f;

    // ldmatrix lane mappings (verified R5/R6)
    const int m_off = ((lane >> 3) & 1) * 8 + (lane & 7);      // A rows
    const int k_off = (lane >> 4) * 8;                          // A k segment
    const int brow  = (lane & 7) + ((lane >> 4) << 3);          // B n row
    const int bk    = ((lane >> 3) & 1) * 8;                    // B k segment

    for (int kh = 0; kh < 5; kh++) {
        __syncthreads();   // previous kh's taps done reading Ws
        {
            const uint4* src = (const uint4*)(g_wh + (size_t)kh * 5 * 64 * WPAD);
            uint4* dst = (uint4*)Ws;
            for (int i = tid; i < 2880; i += 512) dst[i] = src[i];
        }
        __syncthreads();

        #pragma unroll
        for (int kw = 0; kw < 5; kw++) {
            const __half* Ab = Xs + (size_t)(g + kh) * XROW
                                  + (size_t)(px0 + kw) * XPAD;
            // A fragments for all 4 k-chunks
            uint32_t a[4][2][4];
            #pragma unroll
            for (int kt = 0; kt < 4; kt++)
                #pragma unroll
                for (int mt = 0; mt < 2; mt++) {
                    uint32_t ad = smem_u32(Ab + (size_t)(mt * 16 + m_off) * XPAD
                                              + kt * 16 + k_off);
                    asm volatile(
                        "ldmatrix.sync.aligned.m8n8.x4.shared.b16 {%0,%1,%2,%3}, [%4];"
                        : "=r"(a[kt][mt][0]), "=r"(a[kt][mt][1]),
                          "=r"(a[kt][mt][2]), "=r"(a[kt][mt][3])
                        : "r"(ad));
                }
            // B via ldmatrix.x4: regs = {b0,b1 of nt even; b0,b1 of nt odd}
            #pragma unroll
            for (int np = 0; np < 4; np++) {
                #pragma unroll
                for (int kt = 0; kt < 4; kt++) {
                    uint32_t bb[4];
                    uint32_t bd = smem_u32(Ws + (size_t)(kw * 64 + np * 16 + brow) * WPAD
                                              + kt * 16 + bk);
                    asm volatile(
                        "ldmatrix.sync.aligned.m8n8.x4.shared.b16 {%0,%1,%2,%3}, [%4];"
                        : "=r"(bb[0]), "=r"(bb[1]), "=r"(bb[2]), "=r"(bb[3])
                        : "r"(bd));
                    #pragma unroll
                    for (int mt = 0; mt < 2; mt++) {
                        asm volatile(
                            "mma.sync.aligned.m16n8k16.row.col.f32.f16.f16.f32 "
                            "{%0,%1,%2,%3}, {%4,%5,%6,%7}, {%8,%9}, {%0,%1,%2,%3};"
                            : "+f"(acc[mt][2 * np][0]), "+f"(acc[mt][2 * np][1]),
                              "+f"(acc[mt][2 * np][2]), "+f"(acc[mt][2 * np][3])
                            : "r"(a[kt][mt][0]), "r"(a[kt][mt][1]),
                              "r"(a[kt][mt][2]), "r"(a[kt][mt][3]),
                              "r"(bb[0]), "r"(bb[1]));
                        asm volatile(
                            "mma.sync.aligned.m16n8k16.row.col.f32.f16.f16.f32 "
                            "{%0,%1,%2,%3}, {%4,%5,%6,%7}, {%8,%9}, {%0,%1,%2,%3};"
                            : "+f"(acc[mt][2 * np + 1][0]), "+f"(acc[mt][2 * np + 1][1]),
                              "+f"(acc[mt][2 * np + 1][2]), "+f"(acc[mt][2 * np + 1][3])
                            : "r"(a[kt][mt][0]), "r"(a[kt][mt][1]),
                              "r"(a[kt][mt][2]), "r"(a[kt][mt][3]),
                              "r"(bb[2]), "r"(bb[3]));
                    }
                }
            }
        }
    }
    __syncthreads();   // all taps done; Xs region reusable for epilogue

    // ---- epilogue: cosine norm + smem transpose + coalesced fp16 store ----
    float inv[2][2];
    #pragma unroll
    for (int mt = 0; mt < 2; mt++)
        #pragma unroll
        for (int h = 0; h < 2; h++) {
            int p = px0 + mt * 16 + (lane >> 2) + h * 8;
            const float* sp = Ssum + g * 132 + p;
            float s = sp[0] + sp[1] + sp[2] + sp[3] + sp[4];
            inv[mt][h] = rsqrtf(s + 1e-8f);
        }

    float* buf = (float*)(dsm + WS_BYTES) + warp * (64 * 36);
    #pragma unroll
    for (int mt = 0; mt < 2; mt++)
        #pragma unroll
        for (int nt = 0; nt < 8; nt++)
            #pragma unroll
            for (int reg = 0; reg < 4; reg++) {
                int co  = nt * 8 + (lane & 3) * 2 + (reg & 1);
                int pxl = mt * 16 + (lane >> 2) + (reg >> 1) * 8;
                buf[co * 36 + pxl] = acc[mt][nt][reg] * inv[mt][reg >> 1];
            }
    __syncwarp();

    const int y = y0 + g;
    #pragma unroll
    for (int it = 0; it < 16; it++) {
        int row = it * 4 + (lane >> 3);   // cout
        int seg = lane & 7;               // 4-px segment
        float4 v = *(const float4*)&buf[row * 36 + seg * 4];
        uint32_t h01, h23;
        asm("cvt.rn.f16x2.f32 %0, %1, %2;" : "=r"(h01) : "f"(v.y), "f"(v.x));
        asm("cvt.rn.f16x2.f32 %0, %1, %2;" : "=r"(h23) : "f"(v.w), "f"(v.z));
        *(uint2*)&g_ybuf[(((size_t)b * COUT + row) * H_ + y) * W_ + px0 + seg * 4] =
            make_uint2(h01, h23);
    }
}

// ---------------- kernel 3: depthwise 5x5 DoG (zero pad), fp16 input ----------------
__global__ __launch_bounds__(512)
void dog_kernel(float* __restrict__ out) {
    __shared__ float Ts[20 * 132];
    __shared__ float sd[25];

    const int tid = threadIdx.x;
    const int bc  = blockIdx.x;
    const int y0  = blockIdx.y * 16;

    if (tid < 25) sd[tid] = g_dog[tid];

    const __half* src = g_ybuf + (size_t)bc * HW;
    for (int idx = tid; idx < 20 * 66; idx += 512) {
        int rr = idx / 66;
        int c2 = (idx - rr * 66) * 2;         // padded col pair base
        int gy = y0 + rr - 2;
        float2 f = make_float2(0.f, 0.f);
        if (gy >= 0 && gy < H_) {
            int gx = c2 - 2;
            if (gx >= 0 && gx + 1 < W_) {
                f = __half22float2(*(const __half2*)(src + gy * W_ + gx));
            } else {
                if (gx >= 0 && gx < W_)         f.x = __half2float(src[gy * W_ + gx]);
                if (gx + 1 >= 0 && gx + 1 < W_) f.y = __half2float(src[gy * W_ + gx + 1]);
            }
        }
        Ts[rr * 132 + c2]     = f.x;
        Ts[rr * 132 + c2 + 1] = f.y;
    }
    __syncthreads();

    const int row = tid >> 5;
    const int t4  = (tid & 31) * 4;
    float a[4] = {0.f, 0.f, 0.f, 0.f};

    #pragma unroll
    for (int u = 0; u < 5; u++) {
        const float* rp = &Ts[(row + u) * 132 + t4];
        float4 xa = *(const float4*)rp;
        float4 xc = *(const float4*)(rp + 4);
        float xv[8] = {xa.x, xa.y, xa.z, xa.w, xc.x, xc.y, xc.z, xc.w};
        #pragma unroll
        for (int v = 0; v < 5; v++) {
            float dv = sd[u * 5 + v];
            #pragma unroll
            for (int j = 0; j < 4; j++) a[j] = fmaf(dv, xv[v + j], a[j]);
        }
    }
    float4 o = make_float4(a[0], a[1], a[2], a[3]);
    *(float4*)&out[(size_t)bc * HW + (y0 + row) * W_ + t4] = o;
}

// ---------------- launch ----------------
extern "C" void kernel_launch(void* const* d_in, const int* in_sizes, int n_in,
                              void* d_out, int out_size) {
    const float* x = (const float*)d_in[0];
    const float* w = (const float*)d_in[1];
    float* out = (float*)d_out;

    static bool attr_set = false;
    if (!attr_set) {
        cudaFuncSetAttribute(main_mma_kernel,
                             cudaFuncAttributeMaxDynamicSharedMemorySize, DSMEM);
        attr_set = true;
    }

    prep_kernel<<<1600, 64>>>(w);
    main_mma_kernel<<<dim3(32, 16), 512, DSMEM>>>(x);
    dog_kernel<<<dim3(1024, 8), 512>>>(out);
}